// round 1
// baseline (speedup 1.0000x reference)
#include <cuda_runtime.h>
#include <math.h>

#define BB 8
#define CIN 256
#define CO 64
#define VV 128
#define TT 128
#define SY 129   // padded smem row stride (conflict-free)

// ---------------- scratch (device globals; no allocation allowed) ----------
__device__ float g_y  [BB*CO*VV*TT];   // y[b][c][v][t]
__device__ float g_ytr[BB*TT*CO*VV];   // y[b][t][c][v]
__device__ float g_OH [BB*CO*VV*TT];   // unnormalized out_H
__device__ float g_OW [BB*CO*VV*TT];   // unnormalized out_W
__device__ float g_av [BB*CO*VV*TT];   // channel-attention output (conv input)
__device__ float g_mH [BB*VV*TT];
__device__ float g_ZH [BB*VV*TT];
__device__ float g_mW [BB*VV*TT];
__device__ float g_ZW [BB*VV*TT];

// ---------------- kernel 1: y = dc_w @ xp + dc_b ---------------------------
// grid (128 v-rows, 8 b), 256 threads. 64x256 GEMM for one padded row (128 t).
__global__ __launch_bounds__(256) void k_y(const float* __restrict__ x,
                                           const float* __restrict__ w,
                                           const float* __restrict__ bias) {
    __shared__ float xs[32][128];
    __shared__ float ws[64][32];
    int v = blockIdx.x, b = blockIdx.y;
    int tid = threadIdx.x, lane = tid & 31, warp = tid >> 5;
    float acc[8][4];
#pragma unroll
    for (int i = 0; i < 8; i++)
#pragma unroll
        for (int j = 0; j < 4; j++) acc[i][j] = 0.f;
    bool vin = (v >= 1 && v <= 126);
    for (int c0 = 0; c0 < CIN; c0 += 32) {
        for (int i = tid; i < 32*128; i += 256) {
            int ci = i >> 7, t = i & 127;
            float val = 0.f;
            if (vin && t >= 1 && t <= 126)
                val = x[(((size_t)b*CIN + c0 + ci)*126 + (v-1))*126 + (t-1)];
            xs[ci][t] = val;
        }
        for (int i = tid; i < 64*32; i += 256)
            ws[i>>5][i&31] = w[(size_t)(i>>5)*CIN + c0 + (i&31)];
        __syncthreads();
#pragma unroll
        for (int ci = 0; ci < 32; ci++) {
            float xv[4];
#pragma unroll
            for (int j = 0; j < 4; j++) xv[j] = xs[ci][lane + 32*j];
#pragma unroll
            for (int i = 0; i < 8; i++) {
                float wv = ws[warp*8 + i][ci];
#pragma unroll
                for (int j = 0; j < 4; j++) acc[i][j] = fmaf(wv, xv[j], acc[i][j]);
            }
        }
        __syncthreads();
    }
#pragma unroll
    for (int i = 0; i < 8; i++) {
        int o = warp*8 + i;
        float bo = bias[o];
#pragma unroll
        for (int j = 0; j < 4; j++)
            g_y[(((size_t)b*CO + o)*VV + v)*TT + lane + 32*j] = acc[i][j] + bo;
    }
}

// ---------------- kernel 1b: transpose y -> y_tr ----------------------------
// grid (16 tiles, 64 c, 8 b), threads (32,8)
__global__ __launch_bounds__(256) void k_tr() {
    __shared__ float s[32][33];
    int tile = blockIdx.x, c = blockIdx.y, b = blockIdx.z;
    int v0 = (tile >> 2) * 32, t0 = (tile & 3) * 32;
    int tx = threadIdx.x, ty = threadIdx.y;
    const float* src = g_y + ((size_t)(b*CO + c))*VV*TT;
#pragma unroll
    for (int i = 0; i < 32; i += 8)
        s[ty+i][tx] = src[(size_t)(v0+ty+i)*TT + t0 + tx];
    __syncthreads();
    float* dst = g_ytr + (size_t)b*TT*CO*VV + (size_t)c*VV;
#pragma unroll
    for (int i = 0; i < 32; i += 8)
        dst[(size_t)(t0+ty+i)*(CO*VV) + v0 + tx] = s[tx][ty+i];
}

// ---------------- kernel 2: W-attention + channel-attention per (b,v) ------
__global__ __launch_bounds__(256) void k_wc(
    const float* __restrict__ qw, const float* __restrict__ qb,
    const float* __restrict__ kw, const float* __restrict__ kb,
    const float* __restrict__ vw, const float* __restrict__ vb,
    const float* __restrict__ cqw, const float* __restrict__ cqb,
    const float* __restrict__ ckw, const float* __restrict__ ckb,
    const float* __restrict__ cvw, const float* __restrict__ cvb) {
    int v = blockIdx.x, b = blockIdx.y;
    int tid = threadIdx.x, lane = tid & 31, warp = tid >> 5;
    extern __shared__ float sm[];
    float* ys = sm;                 // [64][SY]
    float* s1 = sm + 64*SY;

    // load y[b,:,v,:] slice
    const float* ysrc = g_y + (size_t)b*CO*VV*TT + (size_t)v*TT;
    for (int i = tid; i < 64*128; i += 256) {
        int c = i >> 7, t = i & 127;
        ys[c*SY + t] = ysrc[(size_t)c*VV*TT + t];
    }
    __syncthreads();

    // ---- phase W ----
    float* qs = s1;                 // [8][SY]
    float* ks = s1 + 8*SY;          // [8][SY]
    float* vs = s1 + 16*SY;         // [64][SY]
    float* E  = s1 + 80*SY;         // [128][SY]
    for (int i = tid; i < 2*8*128; i += 256) {
        int which = i >> 10, e = i & 1023;
        int cq = e >> 7, t = e & 127;
        const float* W = which ? kw : qw;
        float acc = which ? kb[cq] : qb[cq];
#pragma unroll 16
        for (int c = 0; c < 64; c++) acc = fmaf(W[cq*64 + c], ys[c*SY + t], acc);
        (which ? ks : qs)[cq*SY + t] = acc;
    }
    for (int i = tid; i < 64*128; i += 256) {
        int c = i >> 7, t = i & 127;
        float acc = vb[c];
#pragma unroll 16
        for (int cc = 0; cc < 64; cc++) acc = fmaf(vw[c*64 + cc], ys[cc*SY + t], acc);
        vs[c*SY + t] = acc;
    }
    __syncthreads();
    for (int i = tid; i < 128*128; i += 256) {
        int t = i >> 7, s = i & 127;
        float acc = 0.f;
#pragma unroll
        for (int c = 0; c < 8; c++) acc = fmaf(qs[c*SY + t], ks[c*SY + s], acc);
        E[t*SY + s] = acc;
    }
    __syncthreads();
    if (tid < 128) {
        int t = tid;
        float m = -INFINITY;
        for (int s = 0; s < 128; s++) m = fmaxf(m, E[t*SY + s]);
        float Z = 0.f;
        for (int s = 0; s < 128; s++) { float p = __expf(E[t*SY + s] - m); E[t*SY + s] = p; Z += p; }
        g_mW[((size_t)b*VV + v)*TT + t] = m;
        g_ZW[((size_t)b*VV + v)*TT + t] = Z;
    }
    __syncthreads();
    {   // O_W[c][t] = sum_s vs[c][s] * P[t][s]
        float acc[8][4];
#pragma unroll
        for (int i = 0; i < 8; i++)
#pragma unroll
            for (int j = 0; j < 4; j++) acc[i][j] = 0.f;
        for (int s = 0; s < 128; s++) {
            float pv[4];
#pragma unroll
            for (int j = 0; j < 4; j++) pv[j] = E[(lane + 32*j)*SY + s];
#pragma unroll
            for (int i = 0; i < 8; i++) {
                float vv = vs[(warp*8 + i)*SY + s];
#pragma unroll
                for (int j = 0; j < 4; j++) acc[i][j] = fmaf(vv, pv[j], acc[i][j]);
            }
        }
        float* dst = g_OW + (size_t)b*CO*VV*TT + (size_t)v*TT;
#pragma unroll
        for (int i = 0; i < 8; i++)
#pragma unroll
            for (int j = 0; j < 4; j++)
                dst[(size_t)(warp*8 + i)*VV*TT + lane + 32*j] = acc[i][j];
    }
    __syncthreads();

    // ---- phase C (channel attention), reuse s1 ----
    float* qc = s1;                 // [64][SY]
    float* kc = s1 + 64*SY;
    float* vc = s1 + 128*SY;
    float* Ec = s1 + 192*SY;        // [64][65]
    for (int i = tid; i < 3*64*128; i += 256) {
        int which = i >> 13, e = i & 8191;
        int c = e >> 7, t = e & 127;
        const float* W  = which == 0 ? cqw : (which == 1 ? ckw : cvw);
        const float* Bv = which == 0 ? cqb : (which == 1 ? ckb : cvb);
        float acc = Bv[c];
#pragma unroll 16
        for (int cc = 0; cc < 64; cc++) acc = fmaf(W[c*64 + cc], ys[cc*SY + t], acc);
        (which == 0 ? qc : (which == 1 ? kc : vc))[c*SY + t] = acc;
    }
    __syncthreads();
    for (int i = tid; i < 64*64; i += 256) {
        int c = i >> 6, d = i & 63;
        float acc = 0.f;
#pragma unroll 16
        for (int t = 0; t < 128; t++) acc = fmaf(qc[c*SY + t], kc[d*SY + t], acc);
        Ec[c*65 + d] = acc;
    }
    __syncthreads();
    if (tid < 64) {
        int c = tid;
        float m = -INFINITY;
        for (int d = 0; d < 64; d++) m = fmaxf(m, Ec[c*65 + d]);
        float Z = 0.f;
        for (int d = 0; d < 64; d++) { float p = __expf(Ec[c*65 + d] - m); Ec[c*65 + d] = p; Z += p; }
        float inv = 1.f / Z;
        for (int d = 0; d < 64; d++) Ec[c*65 + d] *= inv;
    }
    __syncthreads();
    {   // av[c][t] = sum_d attn[c][d] * vc[d][t]
        float acc[8][4];
#pragma unroll
        for (int i = 0; i < 8; i++)
#pragma unroll
            for (int j = 0; j < 4; j++) acc[i][j] = 0.f;
        for (int d = 0; d < 64; d++) {
            float vv[4];
#pragma unroll
            for (int j = 0; j < 4; j++) vv[j] = vc[d*SY + lane + 32*j];
#pragma unroll
            for (int i = 0; i < 8; i++) {
                float a = Ec[(warp*8 + i)*65 + d];
#pragma unroll
                for (int j = 0; j < 4; j++) acc[i][j] = fmaf(a, vv[j], acc[i][j]);
            }
        }
        float* dst = g_av + (size_t)b*CO*VV*TT + (size_t)v*TT;
#pragma unroll
        for (int i = 0; i < 8; i++)
#pragma unroll
            for (int j = 0; j < 4; j++)
                dst[(size_t)(warp*8 + i)*VV*TT + lane + 32*j] = acc[i][j];
    }
}

// ---------------- kernel 3: H-attention per (b,t) ---------------------------
__global__ __launch_bounds__(256) void k_h(
    const float* __restrict__ qw, const float* __restrict__ qb,
    const float* __restrict__ kw, const float* __restrict__ kb,
    const float* __restrict__ vw, const float* __restrict__ vb) {
    int t = blockIdx.x, b = blockIdx.y;
    int tid = threadIdx.x, lane = tid & 31, warp = tid >> 5;
    extern __shared__ float sm[];
    float* ys = sm;                 // [64][SY]  (c x u)
    float* qs = sm + 64*SY;         // [8][SY]   (cq x vrow)
    float* ks = qs + 8*SY;
    float* vs = ks + 8*SY;          // [64][SY]  (c x u)
    float* E  = vs + 64*SY;         // [128][SY] (vrow x u)

    const float* ysrc = g_ytr + ((size_t)b*TT + t)*(CO*VV);
    for (int i = tid; i < 64*128; i += 256) {
        int c = i >> 7, u = i & 127;
        ys[c*SY + u] = ysrc[c*VV + u];
    }
    __syncthreads();
    for (int i = tid; i < 2*8*128; i += 256) {
        int which = i >> 10, e = i & 1023;
        int cq = e >> 7, u = e & 127;
        const float* W = which ? kw : qw;
        float acc = which ? kb[cq] : qb[cq];
#pragma unroll 16
        for (int c = 0; c < 64; c++) acc = fmaf(W[cq*64 + c], ys[c*SY + u], acc);
        (which ? ks : qs)[cq*SY + u] = acc;
    }
    for (int i = tid; i < 64*128; i += 256) {
        int c = i >> 7, u = i & 127;
        float acc = vb[c];
#pragma unroll 16
        for (int cc = 0; cc < 64; cc++) acc = fmaf(vw[c*64 + cc], ys[cc*SY + u], acc);
        vs[c*SY + u] = acc;
    }
    __syncthreads();
    for (int i = tid; i < 128*128; i += 256) {
        int vr = i >> 7, u = i & 127;
        float acc;
        if (vr == u) acc = -1e30f;   // diagonal mask
        else {
            acc = 0.f;
#pragma unroll
            for (int c = 0; c < 8; c++) acc = fmaf(qs[c*SY + vr], ks[c*SY + u], acc);
        }
        E[vr*SY + u] = acc;
    }
    __syncthreads();
    if (tid < 128) {
        int vr = tid;
        float m = -INFINITY;
        for (int u = 0; u < 128; u++) m = fmaxf(m, E[vr*SY + u]);
        float Z = 0.f;
        for (int u = 0; u < 128; u++) { float p = __expf(E[vr*SY + u] - m); E[vr*SY + u] = p; Z += p; }
        g_mH[((size_t)b*VV + vr)*TT + t] = m;
        g_ZH[((size_t)b*VV + vr)*TT + t] = Z;
    }
    __syncthreads();
    {   // O_H[c][vr] = sum_u vs[c][u] * P[vr][u]
        float acc[8][4];
#pragma unroll
        for (int i = 0; i < 8; i++)
#pragma unroll
            for (int j = 0; j < 4; j++) acc[i][j] = 0.f;
        for (int u = 0; u < 128; u++) {
            float pv[4];
#pragma unroll
            for (int j = 0; j < 4; j++) pv[j] = E[(lane + 32*j)*SY + u];
#pragma unroll
            for (int i = 0; i < 8; i++) {
                float vv = vs[(warp*8 + i)*SY + u];
#pragma unroll
                for (int j = 0; j < 4; j++) acc[i][j] = fmaf(vv, pv[j], acc[i][j]);
            }
        }
        float* dst = g_OH + (size_t)b*CO*VV*TT + t;
#pragma unroll
        for (int i = 0; i < 8; i++)
#pragma unroll
            for (int j = 0; j < 4; j++)
                dst[(size_t)(warp*8 + i)*VV*TT + (size_t)(lane + 32*j)*TT] = acc[i][j];
    }
}

// ---------------- kernel 4: 3x3 conv on av + recombine ----------------------
// grid (64 tiles, 4 co-groups, 8 b), threads (16 t, 16 v)
__global__ __launch_bounds__(256) void k_final(
    const float* __restrict__ avw,
    const float* __restrict__ gamma_p, const float* __restrict__ sigma_p,
    float* __restrict__ out) {
    __shared__ float tileS[18][19];
    __shared__ float ws[16*9];
    int b = blockIdx.z, cog = blockIdx.y, tile = blockIdx.x;
    int v0 = (tile >> 3) * 16, t0 = (tile & 7) * 16;
    int tx = threadIdx.x, ty = threadIdx.y;
    int tid = ty*16 + tx;
    int v = v0 + ty, t = t0 + tx;
    float acc[16];
#pragma unroll
    for (int o = 0; o < 16; o++) acc[o] = 0.f;

    for (int ci = 0; ci < 64; ci++) {
        const float* src = g_av + (size_t)(b*CO + ci)*VV*TT;
        for (int i = tid; i < 18*18; i += 256) {
            int r = i / 18, cc = i - r*18;
            int vv2 = v0 - 1 + r, tt2 = t0 - 1 + cc;
            float val = 0.f;
            if (vv2 >= 0 && vv2 < 128 && tt2 >= 0 && tt2 < 128)
                val = src[(size_t)vv2*TT + tt2];
            tileS[r][cc] = val;
        }
        if (tid < 144)
            ws[tid] = avw[(size_t)(cog*16 + tid/9)*(64*9) + ci*9 + (tid % 9)];
        __syncthreads();
        float rv[9];
#pragma unroll
        for (int kr = 0; kr < 3; kr++)
#pragma unroll
            for (int kc2 = 0; kc2 < 3; kc2++)
                rv[kr*3 + kc2] = tileS[ty + kr][tx + kc2];
#pragma unroll
        for (int o = 0; o < 16; o++) {
            float a = acc[o];
#pragma unroll
            for (int kk = 0; kk < 9; kk++) a = fmaf(ws[o*9 + kk], rv[kk], a);
            acc[o] = a;
        }
        __syncthreads();
    }

    float gamma = *gamma_p, sigma = *sigma_p;
    size_t sidx = ((size_t)b*VV + v)*TT + t;
    float mH = g_mH[sidx], ZH = g_ZH[sidx], mW = g_mW[sidx], ZW = g_ZW[sidx];
    float m = fmaxf(mH, mW);
    float eH = __expf(mH - m), eW = __expf(mW - m);
    float inv = gamma / (ZH*eH + ZW*eW);
    float sH = eH * inv, sW = eW * inv;
#pragma unroll
    for (int o = 0; o < 16; o++) {
        size_t idx = (((size_t)b*CO + cog*16 + o)*VV + v)*TT + t;
        out[idx] = g_y[idx] + sH*g_OH[idx] + sW*g_OW[idx] + sigma*acc[o];
    }
}

// ---------------- launch -----------------------------------------------------
extern "C" void kernel_launch(void* const* d_in, const int* in_sizes, int n_in,
                              void* d_out, int out_size) {
    (void)in_sizes; (void)n_in; (void)out_size;
    const float* x    = (const float*)d_in[0];
    const float* dc_w = (const float*)d_in[1];
    const float* dc_b = (const float*)d_in[2];
    const float* q_w  = (const float*)d_in[3];
    const float* q_b  = (const float*)d_in[4];
    const float* k_w  = (const float*)d_in[5];
    const float* k_b  = (const float*)d_in[6];
    const float* v_w  = (const float*)d_in[7];
    const float* v_b  = (const float*)d_in[8];
    const float* gamma= (const float*)d_in[9];
    const float* cq_w = (const float*)d_in[10];
    const float* cq_b = (const float*)d_in[11];
    const float* ck_w = (const float*)d_in[12];
    const float* ck_b = (const float*)d_in[13];
    const float* cv_w = (const float*)d_in[14];
    const float* cv_b = (const float*)d_in[15];
    const float* av_w = (const float*)d_in[16];
    const float* sigma= (const float*)d_in[17];
    float* out = (float*)d_out;

    const int SMEM_WC = (64*SY + 192*SY + 64*65) * 4;   // 148736 B
    const int SMEM_H  = (64*SY + 8*SY + 8*SY + 64*SY + 128*SY) * 4; // 140352 B
    cudaFuncSetAttribute(k_wc, cudaFuncAttributeMaxDynamicSharedMemorySize, SMEM_WC);
    cudaFuncSetAttribute(k_h,  cudaFuncAttributeMaxDynamicSharedMemorySize, SMEM_H);

    k_y  <<<dim3(128, 8), 256>>>(x, dc_w, dc_b);
    k_tr <<<dim3(16, 64, 8), dim3(32, 8)>>>();
    k_wc <<<dim3(128, 8), 256, SMEM_WC>>>(q_w, q_b, k_w, k_b, v_w, v_b,
                                          cq_w, cq_b, ck_w, ck_b, cv_w, cv_b);
    k_h  <<<dim3(128, 8), 256, SMEM_H>>>(q_w, q_b, k_w, k_b, v_w, v_b);
    k_final<<<dim3(64, 4, 8), dim3(16, 16)>>>(av_w, gamma, sigma, out);
}